// round 2
// baseline (speedup 1.0000x reference)
#include <cuda_runtime.h>
#include <cuda_fp16.h>
#include <cuda_bf16.h>
#include <stdint.h>

// Problem shape (fixed by the reference)
#define BATCH 4
#define SEQ   2048
#define EMB   1024

// ---------------- scratch (device globals; no cudaMalloc allowed) ----------
__device__ __half d_Qh[(size_t)BATCH * SEQ * EMB];          // 16 MB
__device__ __half d_Kh[(size_t)BATCH * SEQ * EMB];          // 16 MB
__device__ __half d_Vt[(size_t)BATCH * SEQ * EMB];          // 16 MB  (V transposed: [B][E][S])
__device__ float  d_S [(size_t)BATCH * SEQ * SEQ];          // 64 MB  (scores)
__device__ __half d_P [(size_t)BATCH * SEQ * SEQ];          // 32 MB  (softmax probs)

// ---------------- fp32 -> fp16 convert -------------------------------------
__global__ void cvt_f32_f16(const float* __restrict__ in, __half* __restrict__ out, long n)
{
    long i = (long)blockIdx.x * blockDim.x + threadIdx.x;
    long stride = (long)gridDim.x * blockDim.x;
    for (long idx = i * 4; idx < n; idx += stride * 4) {
        float4 v = *reinterpret_cast<const float4*>(in + idx);
        __half2 h0 = __floats2half2_rn(v.x, v.y);
        __half2 h1 = __floats2half2_rn(v.z, v.w);
        *reinterpret_cast<__half2*>(out + idx)     = h0;
        *reinterpret_cast<__half2*>(out + idx + 2) = h1;
    }
}

// ---------------- V transpose + convert: V[B][S][E] -> Vt[B][E][S] ---------
__global__ void transpose_v(const float* __restrict__ V, __half* __restrict__ Vt)
{
    __shared__ float tile[32][33];
    int b  = blockIdx.z;
    int e0 = blockIdx.x * 32;
    int j0 = blockIdx.y * 32;
    const float* Vb  = V  + (size_t)b * SEQ * EMB;
    __half*      Vtb = Vt + (size_t)b * SEQ * EMB;
    for (int r = threadIdx.y; r < 32; r += 8)
        tile[r][threadIdx.x] = Vb[(size_t)(j0 + r) * EMB + e0 + threadIdx.x];
    __syncthreads();
    for (int r = threadIdx.y; r < 32; r += 8)
        Vtb[(size_t)(e0 + r) * SEQ + j0 + threadIdx.x] = __float2half_rn(tile[threadIdx.x][r]);
}

// ---------------- TN GEMM: C[M,N] = alpha * A[M,K] @ B[N,K]^T ---------------
// fp16 inputs (K-contiguous both operands), fp32 accumulate, fp32 output.
// Tile 128x128x64, 8 warps (2x4), warp tile 64x32, mma.sync m16n8k16.
#define BM 128
#define BN 128
#define BKT 64

__device__ __forceinline__ void ldsm_x4(uint32_t& r0, uint32_t& r1, uint32_t& r2, uint32_t& r3,
                                        const __half* p)
{
    uint32_t sa = (uint32_t)__cvta_generic_to_shared(p);
    asm volatile("ldmatrix.sync.aligned.m8n8.x4.shared.b16 {%0,%1,%2,%3}, [%4];"
                 : "=r"(r0), "=r"(r1), "=r"(r2), "=r"(r3) : "r"(sa));
}

__device__ __forceinline__ void mma16816(float* d, const uint32_t* a, const uint32_t* b)
{
    asm volatile(
        "mma.sync.aligned.m16n8k16.row.col.f32.f16.f16.f32 "
        "{%0,%1,%2,%3}, {%4,%5,%6,%7}, {%8,%9}, {%0,%1,%2,%3};"
        : "+f"(d[0]), "+f"(d[1]), "+f"(d[2]), "+f"(d[3])
        : "r"(a[0]), "r"(a[1]), "r"(a[2]), "r"(a[3]), "r"(b[0]), "r"(b[1]));
}

__global__ void __launch_bounds__(256)
gemm_tn(const __half* __restrict__ A, const __half* __restrict__ B,
        float* __restrict__ C, int M, int N, int K, float alpha)
{
    __shared__ __half As[BM][BKT + 8];
    __shared__ __half Bs[BN][BKT + 8];

    int b = blockIdx.z;
    const __half* Ab = A + (size_t)b * M * K;
    const __half* Bb = B + (size_t)b * N * K;
    float*        Cb = C + (size_t)b * M * N;

    int tm = blockIdx.y * BM;
    int tn = blockIdx.x * BN;
    int tid  = threadIdx.x;
    int wid  = tid >> 5;
    int lane = tid & 31;
    int wm = (wid & 1) * 64;   // warp row offset within tile
    int wn = (wid >> 1) * 32;  // warp col offset within tile

    float acc[4][4][4];
#pragma unroll
    for (int i = 0; i < 4; i++)
#pragma unroll
        for (int j = 0; j < 4; j++)
#pragma unroll
            for (int k = 0; k < 4; k++) acc[i][j][k] = 0.f;

    for (int k0 = 0; k0 < K; k0 += BKT) {
        // cooperative tile load: 128x64 halfs per operand, 16B per thread per iter
#pragma unroll
        for (int it = 0; it < 4; ++it) {
            int idx = tid + it * 256;          // 0..1023
            int row = idx >> 3;                // 0..127
            int col = (idx & 7) * 8;           // 0..56
            *reinterpret_cast<uint4*>(&As[row][col]) =
                *reinterpret_cast<const uint4*>(&Ab[(size_t)(tm + row) * K + k0 + col]);
            *reinterpret_cast<uint4*>(&Bs[row][col]) =
                *reinterpret_cast<const uint4*>(&Bb[(size_t)(tn + row) * K + k0 + col]);
        }
        __syncthreads();

#pragma unroll
        for (int kk = 0; kk < BKT; kk += 16) {
            uint32_t af[4][4];
            uint32_t bf[4][2];
#pragma unroll
            for (int mt = 0; mt < 4; ++mt) {
                const __half* p = &As[wm + mt * 16 + (lane & 15)][kk + ((lane >> 4) << 3)];
                ldsm_x4(af[mt][0], af[mt][1], af[mt][2], af[mt][3], p);
            }
#pragma unroll
            for (int nb = 0; nb < 2; ++nb) {
                uint32_t r0, r1, r2, r3;
                const __half* p = &Bs[wn + nb * 16 + (lane & 15)][kk + ((lane >> 4) << 3)];
                ldsm_x4(r0, r1, r2, r3, p);
                // r0 = n[0:8) k[0:8), r1 = n[8:16) k[0:8),
                // r2 = n[0:8) k[8:16), r3 = n[8:16) k[8:16)
                // mma B fragment = {k-lo, k-hi} of SAME n-block:
                bf[nb * 2 + 0][0] = r0; bf[nb * 2 + 0][1] = r2;
                bf[nb * 2 + 1][0] = r1; bf[nb * 2 + 1][1] = r3;
            }
#pragma unroll
            for (int mt = 0; mt < 4; ++mt)
#pragma unroll
                for (int nt = 0; nt < 4; ++nt)
                    mma16816(acc[mt][nt], af[mt], bf[nt]);
        }
        __syncthreads();
    }

    // epilogue
#pragma unroll
    for (int mt = 0; mt < 4; ++mt) {
#pragma unroll
        for (int nt = 0; nt < 4; ++nt) {
            int r = tm + wm + mt * 16 + (lane >> 2);
            int c = tn + wn + nt * 8 + ((lane & 3) << 1);
            float2 v0 = make_float2(acc[mt][nt][0] * alpha, acc[mt][nt][1] * alpha);
            float2 v1 = make_float2(acc[mt][nt][2] * alpha, acc[mt][nt][3] * alpha);
            *reinterpret_cast<float2*>(&Cb[(size_t)r * N + c])       = v0;
            *reinterpret_cast<float2*>(&Cb[(size_t)(r + 8) * N + c]) = v1;
        }
    }
}

// ---------------- row softmax (+ mask): S fp32 -> P fp16 --------------------
__device__ __forceinline__ float warp_max(float v)
{
#pragma unroll
    for (int o = 16; o > 0; o >>= 1) v = fmaxf(v, __shfl_xor_sync(0xffffffffu, v, o));
    return v;
}
__device__ __forceinline__ float warp_sum(float v)
{
#pragma unroll
    for (int o = 16; o > 0; o >>= 1) v += __shfl_xor_sync(0xffffffffu, v, o);
    return v;
}

__global__ void __launch_bounds__(256)
softmax_kernel(const float* __restrict__ S, const float* __restrict__ mask,
               __half* __restrict__ P)
{
    __shared__ float red[8];
    int row = blockIdx.x;                 // b*SEQ + i
    const float* s = S    + (size_t)row * SEQ;
    const float* m = mask + (size_t)row * SEQ;
    __half*      p = P    + (size_t)row * SEQ;

    int base = threadIdx.x * 8;
    float v[8];
    {
        float4 a  = *reinterpret_cast<const float4*>(s + base);
        float4 b4 = *reinterpret_cast<const float4*>(s + base + 4);
        float4 ma = *reinterpret_cast<const float4*>(m + base);
        float4 mb = *reinterpret_cast<const float4*>(m + base + 4);
        v[0] = a.x  + ma.x; v[1] = a.y  + ma.y; v[2] = a.z  + ma.z; v[3] = a.w  + ma.w;
        v[4] = b4.x + mb.x; v[5] = b4.y + mb.y; v[6] = b4.z + mb.z; v[7] = b4.w + mb.w;
    }
    float mx = v[0];
#pragma unroll
    for (int i = 1; i < 8; i++) mx = fmaxf(mx, v[i]);
    mx = warp_max(mx);
    int wid = threadIdx.x >> 5, lane = threadIdx.x & 31;
    if (lane == 0) red[wid] = mx;
    __syncthreads();
    if (wid == 0) {
        float t = (lane < 8) ? red[lane] : -1e30f;
        t = warp_max(t);
        if (lane == 0) red[0] = t;
    }
    __syncthreads();
    mx = red[0];

    float sum = 0.f;
#pragma unroll
    for (int i = 0; i < 8; i++) { v[i] = __expf(v[i] - mx); sum += v[i]; }
    sum = warp_sum(sum);
    __syncthreads();
    if (lane == 0) red[wid] = sum;
    __syncthreads();
    if (wid == 0) {
        float t = (lane < 8) ? red[lane] : 0.f;
        t = warp_sum(t);
        if (lane == 0) red[0] = t;
    }
    __syncthreads();
    float inv = 1.0f / red[0];

    __half h[8];
#pragma unroll
    for (int i = 0; i < 8; i++) h[i] = __float2half_rn(v[i] * inv);
    *reinterpret_cast<uint4*>(p + base) = *reinterpret_cast<const uint4*>(h);
}

// ---------------- launch -----------------------------------------------------
extern "C" void kernel_launch(void* const* d_in, const int* in_sizes, int n_in,
                              void* d_out, int out_size)
{
    const float* Q    = (const float*)d_in[0];
    const float* K    = (const float*)d_in[1];
    const float* V    = (const float*)d_in[2];
    const float* mask = (const float*)d_in[3];
    float* out = (float*)d_out;

    void *pQh, *pKh, *pVt, *pS, *pP;
    cudaGetSymbolAddress(&pQh, d_Qh);
    cudaGetSymbolAddress(&pKh, d_Kh);
    cudaGetSymbolAddress(&pVt, d_Vt);
    cudaGetSymbolAddress(&pS,  d_S);
    cudaGetSymbolAddress(&pP,  d_P);

    const long nQK = (long)BATCH * SEQ * EMB;

    cvt_f32_f16<<<4096, 256>>>(Q, (__half*)pQh, nQK);
    cvt_f32_f16<<<4096, 256>>>(K, (__half*)pKh, nQK);
    transpose_v<<<dim3(EMB / 32, SEQ / 32, BATCH), dim3(32, 8)>>>(V, (__half*)pVt);

    // S = (1/sqrt(E)) * Q @ K^T ; 1/sqrt(1024) == 0.03125 exactly
    gemm_tn<<<dim3(SEQ / BN, SEQ / BM, BATCH), 256>>>(
        (const __half*)pQh, (const __half*)pKh, (float*)pS,
        SEQ, SEQ, EMB, 0.03125f);

    softmax_kernel<<<BATCH * SEQ, 256>>>((const float*)pS, mask, (__half*)pP);

    // O = P @ V  (V stored transposed, so TN form again)
    gemm_tn<<<dim3(EMB / BN, SEQ / BM, BATCH), 256>>>(
        (const __half*)pP, (const __half*)pVt, out,
        SEQ, EMB, SEQ, 1.0f);
}